// round 1
// baseline (speedup 1.0000x reference)
#include <cuda_runtime.h>
#include <math.h>

// Problem constants (fixed by the reference)
#define NN 50000
#define EE 800000
#define DIN 128
#define HID 128
#define NHEADS 4
#define DHEAD 32
#define NEG_SLOPE 0.2f
#define LN_EPS 1e-5f

// ---------------- scratch (no allocation allowed) ----------------
__device__ float g_h[NN * HID];      // per-layer projected features
__device__ float g_agg[NN * HID];    // aggregated messages
__device__ float g_feat[NN * HID];   // inter-layer activations
__device__ float g_el[NN * NHEADS];
__device__ float g_er[NN * NHEADS];
__device__ float g_m[NN * NHEADS];   // segment max
__device__ float g_s[NN * NHEADS];   // segment sum (denominator)
__device__ float g_ex[EE * NHEADS];  // exp(e - m[dst]) per edge

// ---------------- helpers ----------------
__device__ __forceinline__ void atomicMaxFloat(float* addr, float val) {
    int* ia = (int*)addr;
    int old = *ia;
    while (__int_as_float(old) < val) {
        int assumed = old;
        old = atomicCAS(ia, assumed, __float_as_int(val));
        if (old == assumed) break;
    }
}

// ---------------- kernels ----------------

// Zero agg, init m to -inf and s to 0.
__global__ void init_kernel() {
    int i = blockIdx.x * blockDim.x + threadIdx.x;
    if (i < NN * HID) g_agg[i] = 0.f;
    if (i < NN * NHEADS) { g_m[i] = -INFINITY; g_s[i] = 0.f; }
}

// H = X @ W   (X: [NN, 128] from ptr, W: [128,128]) -> g_h
// 256 threads/block, 64 rows per block, full 128-col tile.
__global__ void gemm_kernel(const float* __restrict__ X,
                            const float* __restrict__ W) {
    __shared__ float xs[64][33];
    __shared__ float ws[32][128];
    int t = threadIdx.x;
    int lane = t & 31;
    int warp = t >> 5;
    int row0 = blockIdx.x * 64;
    float acc[8][4];
#pragma unroll
    for (int i = 0; i < 8; i++)
#pragma unroll
        for (int j = 0; j < 4; j++) acc[i][j] = 0.f;

    for (int k0 = 0; k0 < DIN; k0 += 32) {
        for (int i = t; i < 64 * 32; i += 256) {
            int r = i >> 5, k = i & 31;
            int gr = row0 + r;
            xs[r][k] = (gr < NN) ? X[gr * DIN + k0 + k] : 0.f;
        }
        for (int i = t; i < 32 * 128; i += 256) {
            int k = i >> 7, c = i & 127;
            ws[k][c] = W[(k0 + k) * HID + c];
        }
        __syncthreads();
#pragma unroll
        for (int k = 0; k < 32; k++) {
            float b[4];
#pragma unroll
            for (int j = 0; j < 4; j++) b[j] = ws[k][lane * 4 + j];
#pragma unroll
            for (int i = 0; i < 8; i++) {
                float a = xs[warp * 8 + i][k];
#pragma unroll
                for (int j = 0; j < 4; j++) acc[i][j] += a * b[j];
            }
        }
        __syncthreads();
    }
#pragma unroll
    for (int i = 0; i < 8; i++) {
        int gr = row0 + warp * 8 + i;
        if (gr < NN) {
#pragma unroll
            for (int j = 0; j < 4; j++)
                g_h[gr * HID + lane * 4 + j] = acc[i][j];
        }
    }
}

// el[n][h] = sum_d h[n][h][d]*al[h][d]; er likewise. One node per block (128 thr).
__global__ void elr_kernel(const float* __restrict__ al,
                           const float* __restrict__ ar) {
    int n = blockIdx.x;
    int t = threadIdx.x;
    int head = t >> 5, d = t & 31;
    float h = g_h[n * HID + t];
    float vl = h * al[head * DHEAD + d];
    float vr = h * ar[head * DHEAD + d];
#pragma unroll
    for (int o = 16; o > 0; o >>= 1) {
        vl += __shfl_down_sync(0xffffffffu, vl, o);
        vr += __shfl_down_sync(0xffffffffu, vr, o);
    }
    if (d == 0) {
        g_el[n * NHEADS + head] = vl;
        g_er[n * NHEADS + head] = vr;
    }
}

__device__ __forceinline__ float leaky(float v) {
    return v >= 0.f ? v : NEG_SLOPE * v;
}

// Pass 1: segment max of leaky_relu(el[src]+er[dst]) into g_m[dst]
__global__ void edge_max_kernel(const int* __restrict__ src,
                                const int* __restrict__ dst) {
    int e = blockIdx.x * blockDim.x + threadIdx.x;
    if (e >= EE) return;
    int sn = src[e], dn = dst[e];
#pragma unroll
    for (int h = 0; h < NHEADS; h++) {
        float v = leaky(g_el[sn * NHEADS + h] + g_er[dn * NHEADS + h]);
        atomicMaxFloat(&g_m[dn * NHEADS + h], v);
    }
}

// Pass 2: ex = exp(e - m[dst]) stored per-edge; denom += ex
__global__ void edge_exp_kernel(const int* __restrict__ src,
                                const int* __restrict__ dst) {
    int e = blockIdx.x * blockDim.x + threadIdx.x;
    if (e >= EE) return;
    int sn = src[e], dn = dst[e];
#pragma unroll
    for (int h = 0; h < NHEADS; h++) {
        float v = leaky(g_el[sn * NHEADS + h] + g_er[dn * NHEADS + h]);
        float x = __expf(v - g_m[dn * NHEADS + h]);
        g_ex[e * NHEADS + h] = x;
        atomicAdd(&g_s[dn * NHEADS + h], x);
    }
}

// Pass 3: agg[dst] += h[src] * alpha. One warp per edge; lane d covers
// feature j*32+lane for j=0..3 (head j).
__global__ void edge_agg_kernel(const int* __restrict__ src,
                                const int* __restrict__ dst) {
    int wid = (blockIdx.x * blockDim.x + threadIdx.x) >> 5;
    if (wid >= EE) return;
    int lane = threadIdx.x & 31;
    int sn = src[wid], dn = dst[wid];
#pragma unroll
    for (int j = 0; j < NHEADS; j++) {
        float denom = g_s[dn * NHEADS + j];
        float alpha = g_ex[wid * NHEADS + j] / fmaxf(denom, 1e-9f);
        int d = j * DHEAD + lane;
        atomicAdd(&g_agg[dn * HID + d], g_h[sn * HID + d] * alpha);
    }
}

// bias + layernorm + elu; one node per block (128 threads)
__global__ void ln_elu_kernel(const float* __restrict__ b,
                              const float* __restrict__ g,
                              const float* __restrict__ be,
                              float* __restrict__ out) {
    int n = blockIdx.x;
    int t = threadIdx.x;
    int lane = t & 31, warp = t >> 5;
    __shared__ float red1[4];
    __shared__ float red2[4];

    float v = g_agg[n * HID + t] + b[t];

    float x = v;
#pragma unroll
    for (int o = 16; o > 0; o >>= 1) x += __shfl_down_sync(0xffffffffu, x, o);
    if (lane == 0) red1[warp] = x;
    __syncthreads();
    float mu = (red1[0] + red1[1] + red1[2] + red1[3]) * (1.f / HID);

    float c = v - mu;
    float x2 = c * c;
#pragma unroll
    for (int o = 16; o > 0; o >>= 1) x2 += __shfl_down_sync(0xffffffffu, x2, o);
    if (lane == 0) red2[warp] = x2;
    __syncthreads();
    float var = (red2[0] + red2[1] + red2[2] + red2[3]) * (1.f / HID);

    float y = c * rsqrtf(var + LN_EPS) * g[t] + be[t];
    y = y > 0.f ? y : expm1f(y);
    out[n * HID + t] = y;
}

// ---------------- launch ----------------
static void run_layer(const float* feats_in, const float* W, const float* al,
                      const float* ar, const float* b, const float* g,
                      const float* be, float* out) {
    int initN = NN * HID;
    init_kernel<<<(initN + 255) / 256, 256>>>();
    gemm_kernel<<<(NN + 63) / 64, 256>>>(feats_in, W);
    elr_kernel<<<NN, 128>>>(al, ar);
    edge_max_kernel<<<(EE + 255) / 256, 256>>>(
        (const int*)nullptr, (const int*)nullptr);  // placeholder replaced below
    (void)0;
}

static const int* gs_src;
static const int* gs_dst;

static void run_layer2(const float* feats_in, const float* W, const float* al,
                       const float* ar, const float* b, const float* g,
                       const float* be, float* out) {
    int initN = NN * HID;
    init_kernel<<<(initN + 255) / 256, 256>>>();
    gemm_kernel<<<(NN + 63) / 64, 256>>>(feats_in, W);
    elr_kernel<<<NN, 128>>>(al, ar);
    edge_max_kernel<<<(EE + 255) / 256, 256>>>(gs_src, gs_dst);
    edge_exp_kernel<<<(EE + 255) / 256, 256>>>(gs_src, gs_dst);
    // one warp per edge -> EE*32 threads
    long long thr = (long long)EE * 32;
    edge_agg_kernel<<<(int)((thr + 255) / 256), 256>>>(gs_src, gs_dst);
    ln_elu_kernel<<<NN, 128>>>(b, g, be, out);
}

extern "C" void kernel_launch(void* const* d_in, const int* in_sizes, int n_in,
                              void* d_out, int out_size) {
    const float* features = (const float*)d_in[0];
    const int* src = (const int*)d_in[1];
    const int* dst = (const int*)d_in[2];
    const float* W0 = (const float*)d_in[3];
    const float* al0 = (const float*)d_in[4];
    const float* ar0 = (const float*)d_in[5];
    const float* b0 = (const float*)d_in[6];
    const float* g0 = (const float*)d_in[7];
    const float* be0 = (const float*)d_in[8];
    const float* W1 = (const float*)d_in[9];
    const float* al1 = (const float*)d_in[10];
    const float* ar1 = (const float*)d_in[11];
    const float* b1 = (const float*)d_in[12];
    const float* g1 = (const float*)d_in[13];
    const float* be1 = (const float*)d_in[14];
    float* out = (float*)d_out;

    gs_src = src;
    gs_dst = dst;

    // layer 0 -> g_feat
    float* feat_ptr = nullptr;
    cudaGetSymbolAddress((void**)&feat_ptr, g_feat);

    run_layer2(features, W0, al0, ar0, b0, g0, be0, feat_ptr);
    run_layer2(feat_ptr, W1, al1, ar1, b1, g1, be1, out);
}

// round 2
// speedup vs baseline: 1.4996x; 1.4996x over previous
#include <cuda_runtime.h>
#include <math.h>

#define NN 50000
#define EE 800000
#define DIN 128
#define HID 128
#define NHEADS 4
#define DHEAD 32
#define NEG_SLOPE 0.2f
#define LN_EPS 1e-5f

// ---------------- scratch ----------------
__device__ float g_h[NN * HID];        // projected features for current layer
__device__ float g_feat[NN * HID];     // inter-layer activations
__device__ float g_el[NN * NHEADS];    // attention logits (src side)
__device__ float g_er[NN * NHEADS];    // attention logits (dst side)
__device__ int   g_count[NN];
__device__ int   g_cursor[NN];
__device__ int   g_rowstart[NN + 1];
__device__ int   g_csrc[EE];           // CSR payload: src node of each in-edge, grouped by dst

__device__ __forceinline__ float leaky(float v) {
    return v >= 0.f ? v : NEG_SLOPE * v;
}

// ---------------- CSR build ----------------
__global__ void zero_counts() {
    int i = blockIdx.x * blockDim.x + threadIdx.x;
    if (i < NN) g_count[i] = 0;
}

__global__ void hist_kernel(const int* __restrict__ dst) {
    int e = blockIdx.x * blockDim.x + threadIdx.x;
    if (e < EE) atomicAdd(&g_count[dst[e]], 1);
}

// single block, 1024 threads: exclusive scan over g_count -> g_rowstart, g_cursor
__global__ void scan_kernel() {
    const int T = 1024;
    const int CH = (NN + T - 1) / T;  // 49
    int t = threadIdx.x;
    int base = t * CH;
    int sum = 0;
    for (int i = 0; i < CH; i++) {
        int idx = base + i;
        if (idx < NN) sum += g_count[idx];
    }
    __shared__ int sm[T];
    sm[t] = sum;
    __syncthreads();
    for (int off = 1; off < T; off <<= 1) {
        int v = (t >= off) ? sm[t - off] : 0;
        __syncthreads();
        sm[t] += v;
        __syncthreads();
    }
    int run = sm[t] - sum;  // exclusive prefix for this chunk
    for (int i = 0; i < CH; i++) {
        int idx = base + i;
        if (idx < NN) {
            g_rowstart[idx] = run;
            g_cursor[idx] = run;
            run += g_count[idx];
        }
    }
    if (t == T - 1) g_rowstart[NN] = sm[T - 1];
}

__global__ void scatter_kernel(const int* __restrict__ src,
                               const int* __restrict__ dst) {
    int e = blockIdx.x * blockDim.x + threadIdx.x;
    if (e < EE) {
        int pos = atomicAdd(&g_cursor[dst[e]], 1);
        g_csrc[pos] = src[e];
    }
}

// ---------------- GEMM + fused el/er ----------------
// H = X @ W (X:[NN,128], W:[128,128]) -> g_h; el/er computed in epilogue.
__global__ void gemm_elr_kernel(const float* __restrict__ X,
                                const float* __restrict__ W,
                                const float* __restrict__ al,
                                const float* __restrict__ ar) {
    __shared__ float xs[64][33];
    __shared__ float ws[32][128];
    int t = threadIdx.x;
    int lane = t & 31;
    int warp = t >> 5;
    int row0 = blockIdx.x * 64;
    float acc[8][4];
#pragma unroll
    for (int i = 0; i < 8; i++)
#pragma unroll
        for (int j = 0; j < 4; j++) acc[i][j] = 0.f;

    for (int k0 = 0; k0 < DIN; k0 += 32) {
        for (int i = t; i < 64 * 32; i += 256) {
            int r = i >> 5, k = i & 31;
            int gr = row0 + r;
            xs[r][k] = (gr < NN) ? X[gr * DIN + k0 + k] : 0.f;
        }
        for (int i = t; i < 32 * 128; i += 256) {
            int k = i >> 7, c = i & 127;
            ws[k][c] = W[(k0 + k) * HID + c];
        }
        __syncthreads();
#pragma unroll
        for (int k = 0; k < 32; k++) {
            float bb[4];
#pragma unroll
            for (int j = 0; j < 4; j++) bb[j] = ws[k][lane * 4 + j];
#pragma unroll
            for (int i = 0; i < 8; i++) {
                float a = xs[warp * 8 + i][k];
#pragma unroll
                for (int j = 0; j < 4; j++) acc[i][j] += a * bb[j];
            }
        }
        __syncthreads();
    }

    int head = lane >> 3;        // 8 lanes per head-segment of 32 cols
    int dbase = (lane & 7) * 4;  // position within head
#pragma unroll
    for (int i = 0; i < 8; i++) {
        int gr = row0 + warp * 8 + i;
        if (gr < NN) {
            float vl = 0.f, vr = 0.f;
#pragma unroll
            for (int j = 0; j < 4; j++) {
                float hv = acc[i][j];
                g_h[gr * HID + lane * 4 + j] = hv;
                vl += hv * al[head * DHEAD + dbase + j];
                vr += hv * ar[head * DHEAD + dbase + j];
            }
#pragma unroll
            for (int o = 4; o > 0; o >>= 1) {
                vl += __shfl_xor_sync(0xffffffffu, vl, o);
                vr += __shfl_xor_sync(0xffffffffu, vr, o);
            }
            if ((lane & 7) == 0) {
                g_el[gr * NHEADS + head] = vl;
                g_er[gr * NHEADS + head] = vr;
            }
        }
    }
}

// ---------------- per-node gather + softmax + aggregate + LN + ELU ----------------
// One block (128 threads) per dst node. No atomics.
__global__ void node_kernel(const float* __restrict__ b,
                            const float* __restrict__ g,
                            const float* __restrict__ be,
                            float* __restrict__ out) {
    int n = blockIdx.x;
    int t = threadIdx.x;
    int lane = t & 31;
    int warp = t >> 5;   // == head for this thread's feature column
    int beg = g_rowstart[n];
    int end = g_rowstart[n + 1];

    __shared__ float s_m[NHEADS], s_invd[NHEADS];
    __shared__ float red1[4], red2[4];

    float4 er4 = ((const float4*)g_er)[n];  // broadcast load

    // pass 1 (warp 0): per-head max then denominator
    if (warp == 0) {
        float m0 = -INFINITY, m1 = -INFINITY, m2 = -INFINITY, m3 = -INFINITY;
        for (int k = beg + lane; k < end; k += 32) {
            int s = g_csrc[k];
            float4 el4 = ((const float4*)g_el)[s];
            m0 = fmaxf(m0, leaky(el4.x + er4.x));
            m1 = fmaxf(m1, leaky(el4.y + er4.y));
            m2 = fmaxf(m2, leaky(el4.z + er4.z));
            m3 = fmaxf(m3, leaky(el4.w + er4.w));
        }
#pragma unroll
        for (int o = 16; o > 0; o >>= 1) {
            m0 = fmaxf(m0, __shfl_xor_sync(0xffffffffu, m0, o));
            m1 = fmaxf(m1, __shfl_xor_sync(0xffffffffu, m1, o));
            m2 = fmaxf(m2, __shfl_xor_sync(0xffffffffu, m2, o));
            m3 = fmaxf(m3, __shfl_xor_sync(0xffffffffu, m3, o));
        }
        float d0 = 0.f, d1 = 0.f, d2 = 0.f, d3 = 0.f;
        for (int k = beg + lane; k < end; k += 32) {
            int s = g_csrc[k];
            float4 el4 = ((const float4*)g_el)[s];
            d0 += __expf(leaky(el4.x + er4.x) - m0);
            d1 += __expf(leaky(el4.y + er4.y) - m1);
            d2 += __expf(leaky(el4.z + er4.z) - m2);
            d3 += __expf(leaky(el4.w + er4.w) - m3);
        }
#pragma unroll
        for (int o = 16; o > 0; o >>= 1) {
            d0 += __shfl_xor_sync(0xffffffffu, d0, o);
            d1 += __shfl_xor_sync(0xffffffffu, d1, o);
            d2 += __shfl_xor_sync(0xffffffffu, d2, o);
            d3 += __shfl_xor_sync(0xffffffffu, d3, o);
        }
        if (lane == 0) {
            s_m[0] = m0; s_m[1] = m1; s_m[2] = m2; s_m[3] = m3;
            s_invd[0] = 1.f / fmaxf(d0, 1e-9f);
            s_invd[1] = 1.f / fmaxf(d1, 1e-9f);
            s_invd[2] = 1.f / fmaxf(d2, 1e-9f);
            s_invd[3] = 1.f / fmaxf(d3, 1e-9f);
        }
    }
    __syncthreads();

    float m = s_m[warp];
    float invd = s_invd[warp];
    float er_h = (warp == 0) ? er4.x : (warp == 1) ? er4.y : (warp == 2) ? er4.z : er4.w;

    // pass 2: all 128 threads accumulate feature column t
    float acc = 0.f;
#pragma unroll 4
    for (int k = beg; k < end; k++) {
        int s = g_csrc[k];                         // broadcast
        float el_h = g_el[s * NHEADS + warp];      // broadcast within warp
        float w = __expf(leaky(el_h + er_h) - m) * invd;
        acc += g_h[s * HID + t] * w;               // coalesced 512B row
    }

    // bias + LayerNorm + ELU
    float v = acc + b[t];
    float x = v;
#pragma unroll
    for (int o = 16; o > 0; o >>= 1) x += __shfl_down_sync(0xffffffffu, x, o);
    if (lane == 0) red1[warp] = x;
    __syncthreads();
    float mu = (red1[0] + red1[1] + red1[2] + red1[3]) * (1.f / HID);

    float c = v - mu;
    float x2 = c * c;
#pragma unroll
    for (int o = 16; o > 0; o >>= 1) x2 += __shfl_down_sync(0xffffffffu, x2, o);
    if (lane == 0) red2[warp] = x2;
    __syncthreads();
    float var = (red2[0] + red2[1] + red2[2] + red2[3]) * (1.f / HID);

    float y = c * rsqrtf(var + LN_EPS) * g[t] + be[t];
    y = y > 0.f ? y : expm1f(y);
    out[n * HID + t] = y;
}

// ---------------- launch ----------------
static void run_layer(const float* feats_in, const float* W, const float* al,
                      const float* ar, const float* b, const float* g,
                      const float* be, float* out) {
    gemm_elr_kernel<<<(NN + 63) / 64, 256>>>(feats_in, W, al, ar);
    node_kernel<<<NN, 128>>>(b, g, be, out);
}

extern "C" void kernel_launch(void* const* d_in, const int* in_sizes, int n_in,
                              void* d_out, int out_size) {
    const float* features = (const float*)d_in[0];
    const int* src = (const int*)d_in[1];
    const int* dst = (const int*)d_in[2];
    const float* W0 = (const float*)d_in[3];
    const float* al0 = (const float*)d_in[4];
    const float* ar0 = (const float*)d_in[5];
    const float* b0 = (const float*)d_in[6];
    const float* g0 = (const float*)d_in[7];
    const float* be0 = (const float*)d_in[8];
    const float* W1 = (const float*)d_in[9];
    const float* al1 = (const float*)d_in[10];
    const float* ar1 = (const float*)d_in[11];
    const float* b1 = (const float*)d_in[12];
    const float* g1 = (const float*)d_in[13];
    const float* be1 = (const float*)d_in[14];
    float* out = (float*)d_out;

    // CSR build (same graph both layers)
    zero_counts<<<(NN + 255) / 256, 256>>>();
    hist_kernel<<<(EE + 255) / 256, 256>>>(dst);
    scan_kernel<<<1, 1024>>>();
    scatter_kernel<<<(EE + 255) / 256, 256>>>(src, dst);

    float* feat_ptr = nullptr;
    cudaGetSymbolAddress((void**)&feat_ptr, g_feat);

    run_layer(features, W0, al0, ar0, b0, g0, be0, feat_ptr);
    run_layer(feat_ptr, W1, al1, ar1, b1, g1, be1, out);
}

// round 3
// speedup vs baseline: 1.8018x; 1.2015x over previous
#include <cuda_runtime.h>
#include <math.h>

#define NN 50000
#define EE 800000
#define DIN 128
#define HID 128
#define NHEADS 4
#define DHEAD 32
#define NEG_SLOPE 0.2f
#define LN_EPS 1e-5f
#define CHUNK 256

// ---------------- scratch ----------------
__device__ float g_h[NN * HID];        // projected features for current layer
__device__ float g_feat[NN * HID];     // inter-layer activations
__device__ float g_el[NN * NHEADS];    // attention logits (src side)
__device__ float g_er[NN * NHEADS];    // attention logits (dst side)
__device__ int   g_count[NN];
__device__ int   g_cursor[NN];
__device__ int   g_rowstart[NN + 1];
__device__ int   g_csrc[EE];           // CSR payload: src node of each in-edge, grouped by dst

__device__ __forceinline__ float leaky(float v) {
    return v >= 0.f ? v : NEG_SLOPE * v;
}

// ---------------- CSR build ----------------
__global__ void zero_counts() {
    int i = blockIdx.x * blockDim.x + threadIdx.x;
    if (i < NN) g_count[i] = 0;
}

__global__ void hist_kernel(const int* __restrict__ dst) {
    int e = blockIdx.x * blockDim.x + threadIdx.x;
    if (e < EE) atomicAdd(&g_count[dst[e]], 1);
}

// single block, 1024 threads: exclusive scan over g_count -> g_rowstart, g_cursor
__global__ void scan_kernel() {
    const int T = 1024;
    const int CH = (NN + T - 1) / T;  // 49
    int t = threadIdx.x;
    int base = t * CH;
    int sum = 0;
    for (int i = 0; i < CH; i++) {
        int idx = base + i;
        if (idx < NN) sum += g_count[idx];
    }
    __shared__ int sm[T];
    sm[t] = sum;
    __syncthreads();
    for (int off = 1; off < T; off <<= 1) {
        int v = (t >= off) ? sm[t - off] : 0;
        __syncthreads();
        sm[t] += v;
        __syncthreads();
    }
    int run = sm[t] - sum;  // exclusive prefix for this chunk
    for (int i = 0; i < CH; i++) {
        int idx = base + i;
        if (idx < NN) {
            g_rowstart[idx] = run;
            g_cursor[idx] = run;
            run += g_count[idx];
        }
    }
    if (t == T - 1) g_rowstart[NN] = sm[T - 1];
}

__global__ void scatter_kernel(const int* __restrict__ src,
                               const int* __restrict__ dst) {
    int e = blockIdx.x * blockDim.x + threadIdx.x;
    if (e < EE) {
        int pos = atomicAdd(&g_cursor[dst[e]], 1);
        g_csrc[pos] = src[e];
    }
}

// ---------------- GEMM + fused el/er ----------------
// H = X @ W (X:[NN,128], W:[128,128]) -> g_h; el/er computed in epilogue.
__global__ void gemm_elr_kernel(const float* __restrict__ X,
                                const float* __restrict__ W,
                                const float* __restrict__ al,
                                const float* __restrict__ ar) {
    __shared__ float xs[64][33];
    __shared__ float ws[32][128];
    int t = threadIdx.x;
    int lane = t & 31;
    int warp = t >> 5;
    int row0 = blockIdx.x * 64;
    float acc[8][4];
#pragma unroll
    for (int i = 0; i < 8; i++)
#pragma unroll
        for (int j = 0; j < 4; j++) acc[i][j] = 0.f;

    for (int k0 = 0; k0 < DIN; k0 += 32) {
        for (int i = t; i < 64 * 32; i += 256) {
            int r = i >> 5, k = i & 31;
            int gr = row0 + r;
            xs[r][k] = (gr < NN) ? X[gr * DIN + k0 + k] : 0.f;
        }
        for (int i = t; i < 32 * 128; i += 256) {
            int k = i >> 7, c = i & 127;
            ws[k][c] = W[(k0 + k) * HID + c];
        }
        __syncthreads();
#pragma unroll
        for (int k = 0; k < 32; k++) {
            float bb[4];
#pragma unroll
            for (int j = 0; j < 4; j++) bb[j] = ws[k][lane * 4 + j];
#pragma unroll
            for (int i = 0; i < 8; i++) {
                float a = xs[warp * 8 + i][k];
#pragma unroll
                for (int j = 0; j < 4; j++) acc[i][j] += a * bb[j];
            }
        }
        __syncthreads();
    }

    int head = lane >> 3;        // 8 lanes per head-segment of 32 cols
    int dbase = (lane & 7) * 4;  // position within head
#pragma unroll
    for (int i = 0; i < 8; i++) {
        int gr = row0 + warp * 8 + i;
        if (gr < NN) {
            float vl = 0.f, vr = 0.f;
#pragma unroll
            for (int j = 0; j < 4; j++) {
                float hv = acc[i][j];
                g_h[gr * HID + lane * 4 + j] = hv;
                vl += hv * al[head * DHEAD + dbase + j];
                vr += hv * ar[head * DHEAD + dbase + j];
            }
#pragma unroll
            for (int o = 4; o > 0; o >>= 1) {
                vl += __shfl_xor_sync(0xffffffffu, vl, o);
                vr += __shfl_xor_sync(0xffffffffu, vr, o);
            }
            if ((lane & 7) == 0) {
                g_el[gr * NHEADS + head] = vl;
                g_er[gr * NHEADS + head] = vr;
            }
        }
    }
}

// ---------------- single-pass per-node gather + softmax + aggregate + LN + ELU ----
// One block (128 threads) per dst node. Softmax done WITHOUT max-shift and with
// post-scaled denominator:  out = (sum_e h[src]*exp(e)) * 1/(sum_e exp(e)).
__global__ void node_kernel(const float* __restrict__ b,
                            const float* __restrict__ g,
                            const float* __restrict__ be,
                            float* __restrict__ out) {
    int n = blockIdx.x;
    int t = threadIdx.x;
    int lane = t & 31;
    int warp = t >> 5;   // == head for this thread's feature column
    int beg = g_rowstart[n];
    int end = g_rowstart[n + 1];

    __shared__ int s_idx[CHUNK];
    __shared__ float s_w[NHEADS][CHUNK];
    __shared__ float red1[4], red2[4];

    float er_h = g_er[n * NHEADS + warp];

    float acc = 0.f;
    float dpart = 0.f;  // per-lane partial of softmax denominator (this head)

    for (int c0 = beg; c0 < end; c0 += CHUNK) {
        int cnt = min(CHUNK, end - c0);
        __syncthreads();  // protect smem reuse across chunks
        // cooperative index stage
        for (int i = t; i < cnt; i += 128) s_idx[i] = g_csrc[c0 + i];
        __syncthreads();
        // per-head edge weights (each warp = one head)
        for (int i = lane; i < cnt; i += 32) {
            int s = s_idx[i];
            float w = __expf(leaky(g_el[s * NHEADS + warp] + er_h));
            s_w[warp][i] = w;
            dpart += w;
        }
        __syncthreads();
        // streaming accumulation: all 128 threads, column t
        int i = 0;
        for (; i + 4 <= cnt; i += 4) {
            int s0 = s_idx[i],     s1 = s_idx[i + 1];
            int s2 = s_idx[i + 2], s3 = s_idx[i + 3];
            float w0 = s_w[warp][i],     w1 = s_w[warp][i + 1];
            float w2 = s_w[warp][i + 2], w3 = s_w[warp][i + 3];
            float h0 = g_h[s0 * HID + t];
            float h1 = g_h[s1 * HID + t];
            float h2 = g_h[s2 * HID + t];
            float h3 = g_h[s3 * HID + t];
            acc += h0 * w0;
            acc += h1 * w1;
            acc += h2 * w2;
            acc += h3 * w3;
        }
        for (; i < cnt; i++) acc += g_h[s_idx[i] * HID + t] * s_w[warp][i];
    }

    // warp-reduce denominator (lanes hold strided partials of the same head)
#pragma unroll
    for (int o = 16; o > 0; o >>= 1)
        dpart += __shfl_xor_sync(0xffffffffu, dpart, o);
    float invd = 1.f / fmaxf(dpart, 1e-9f);

    // bias + LayerNorm + ELU
    float v = acc * invd + b[t];
    float x = v;
#pragma unroll
    for (int o = 16; o > 0; o >>= 1) x += __shfl_down_sync(0xffffffffu, x, o);
    if (lane == 0) red1[warp] = x;
    __syncthreads();
    float mu = (red1[0] + red1[1] + red1[2] + red1[3]) * (1.f / HID);

    float c = v - mu;
    float x2 = c * c;
#pragma unroll
    for (int o = 16; o > 0; o >>= 1) x2 += __shfl_down_sync(0xffffffffu, x2, o);
    if (lane == 0) red2[warp] = x2;
    __syncthreads();
    float var = (red2[0] + red2[1] + red2[2] + red2[3]) * (1.f / HID);

    float y = c * rsqrtf(var + LN_EPS) * g[t] + be[t];
    y = y > 0.f ? y : expm1f(y);
    out[n * HID + t] = y;
}

// ---------------- launch ----------------
static void run_layer(const float* feats_in, const float* W, const float* al,
                      const float* ar, const float* b, const float* g,
                      const float* be, float* out) {
    gemm_elr_kernel<<<(NN + 63) / 64, 256>>>(feats_in, W, al, ar);
    node_kernel<<<NN, 128>>>(b, g, be, out);
}

extern "C" void kernel_launch(void* const* d_in, const int* in_sizes, int n_in,
                              void* d_out, int out_size) {
    const float* features = (const float*)d_in[0];
    const int* src = (const int*)d_in[1];
    const int* dst = (const int*)d_in[2];
    const float* W0 = (const float*)d_in[3];
    const float* al0 = (const float*)d_in[4];
    const float* ar0 = (const float*)d_in[5];
    const float* b0 = (const float*)d_in[6];
    const float* g0 = (const float*)d_in[7];
    const float* be0 = (const float*)d_in[8];
    const float* W1 = (const float*)d_in[9];
    const float* al1 = (const float*)d_in[10];
    const float* ar1 = (const float*)d_in[11];
    const float* b1 = (const float*)d_in[12];
    const float* g1 = (const float*)d_in[13];
    const float* be1 = (const float*)d_in[14];
    float* out = (float*)d_out;

    // CSR build (same graph both layers)
    zero_counts<<<(NN + 255) / 256, 256>>>();
    hist_kernel<<<(EE + 255) / 256, 256>>>(dst);
    scan_kernel<<<1, 1024>>>();
    scatter_kernel<<<(EE + 255) / 256, 256>>>(src, dst);

    float* feat_ptr = nullptr;
    cudaGetSymbolAddress((void**)&feat_ptr, g_feat);

    run_layer(features, W0, al0, ar0, b0, g0, be0, feat_ptr);
    run_layer(feat_ptr, W1, al1, ar1, b1, g1, be1, out);
}

// round 4
// speedup vs baseline: 2.3109x; 1.2825x over previous
#include <cuda_runtime.h>
#include <math.h>

#define NN 50000
#define EE 800000
#define DIN 128
#define HID 128
#define NHEADS 4
#define DHEAD 32
#define NEG_SLOPE 0.2f
#define LN_EPS 1e-5f
#define WPB 8   // warps (nodes) per block in node_kernel

// ---------------- scratch ----------------
__device__ float g_h[NN * HID];        // projected features for current layer
__device__ float g_feat[NN * HID];     // inter-layer activations
__device__ float g_el[NN * NHEADS];    // attention logits (src side)
__device__ float g_er[NN * NHEADS];    // attention logits (dst side)
__device__ int   g_count[NN];
__device__ int   g_cursor[NN];
__device__ int   g_rowstart[NN + 1];
__device__ int   g_csrc[EE];           // CSR payload: src node per in-edge, grouped by dst

__device__ __forceinline__ float leaky(float v) {
    return v >= 0.f ? v : NEG_SLOPE * v;
}

// ---------------- CSR build ----------------
__global__ void zero_counts() {
    int i = blockIdx.x * blockDim.x + threadIdx.x;
    if (i < NN) g_count[i] = 0;
}

__global__ void hist_kernel(const int* __restrict__ dst) {
    int e = blockIdx.x * blockDim.x + threadIdx.x;
    if (e < EE) atomicAdd(&g_count[dst[e]], 1);
}

// single block, 1024 threads: exclusive scan over g_count -> g_rowstart, g_cursor
__global__ void scan_kernel() {
    const int T = 1024;
    const int CH = (NN + T - 1) / T;  // 49
    int t = threadIdx.x;
    int base = t * CH;
    int sum = 0;
    for (int i = 0; i < CH; i++) {
        int idx = base + i;
        if (idx < NN) sum += g_count[idx];
    }
    __shared__ int sm[T];
    sm[t] = sum;
    __syncthreads();
    for (int off = 1; off < T; off <<= 1) {
        int v = (t >= off) ? sm[t - off] : 0;
        __syncthreads();
        sm[t] += v;
        __syncthreads();
    }
    int run = sm[t] - sum;  // exclusive prefix for this chunk
    for (int i = 0; i < CH; i++) {
        int idx = base + i;
        if (idx < NN) {
            g_rowstart[idx] = run;
            g_cursor[idx] = run;
            run += g_count[idx];
        }
    }
    if (t == T - 1) g_rowstart[NN] = sm[T - 1];
}

__global__ void scatter_kernel(const int* __restrict__ src,
                               const int* __restrict__ dst) {
    int e = blockIdx.x * blockDim.x + threadIdx.x;
    if (e < EE) {
        int pos = atomicAdd(&g_cursor[dst[e]], 1);
        g_csrc[pos] = src[e];
    }
}

// ---------------- GEMM + fused el/er ----------------
__global__ void gemm_elr_kernel(const float* __restrict__ X,
                                const float* __restrict__ W,
                                const float* __restrict__ al,
                                const float* __restrict__ ar) {
    __shared__ float xs[64][33];
    __shared__ float ws[32][128];
    int t = threadIdx.x;
    int lane = t & 31;
    int warp = t >> 5;
    int row0 = blockIdx.x * 64;
    float acc[8][4];
#pragma unroll
    for (int i = 0; i < 8; i++)
#pragma unroll
        for (int j = 0; j < 4; j++) acc[i][j] = 0.f;

    for (int k0 = 0; k0 < DIN; k0 += 32) {
        for (int i = t; i < 64 * 32; i += 256) {
            int r = i >> 5, k = i & 31;
            int gr = row0 + r;
            xs[r][k] = (gr < NN) ? X[gr * DIN + k0 + k] : 0.f;
        }
        for (int i = t; i < 32 * 128; i += 256) {
            int k = i >> 7, c = i & 127;
            ws[k][c] = W[(k0 + k) * HID + c];
        }
        __syncthreads();
#pragma unroll
        for (int k = 0; k < 32; k++) {
            float bb[4];
#pragma unroll
            for (int j = 0; j < 4; j++) bb[j] = ws[k][lane * 4 + j];
#pragma unroll
            for (int i = 0; i < 8; i++) {
                float a = xs[warp * 8 + i][k];
#pragma unroll
                for (int j = 0; j < 4; j++) acc[i][j] += a * bb[j];
            }
        }
        __syncthreads();
    }

    int head = lane >> 3;
    int dbase = (lane & 7) * 4;
#pragma unroll
    for (int i = 0; i < 8; i++) {
        int gr = row0 + warp * 8 + i;
        if (gr < NN) {
            float vl = 0.f, vr = 0.f;
#pragma unroll
            for (int j = 0; j < 4; j++) {
                float hv = acc[i][j];
                g_h[gr * HID + lane * 4 + j] = hv;
                vl += hv * al[head * DHEAD + dbase + j];
                vr += hv * ar[head * DHEAD + dbase + j];
            }
#pragma unroll
            for (int o = 4; o > 0; o >>= 1) {
                vl += __shfl_xor_sync(0xffffffffu, vl, o);
                vr += __shfl_xor_sync(0xffffffffu, vr, o);
            }
            if ((lane & 7) == 0) {
                g_el[gr * NHEADS + head] = vl;
                g_er[gr * NHEADS + head] = vr;
            }
        }
    }
}

// ---------------- warp-per-node gather + softmax + aggregate + LN + ELU --------
// One warp per dst node; lane owns feature cols [4*lane, 4*lane+4), head = lane>>3.
// out = (sum_e h[src]*exp(e)) * 1/(sum_e exp(e)); every lane sweeps all edges so
// the per-head denominator is complete per-lane (no reduction needed).
__global__ void __launch_bounds__(WPB * 32) node_kernel(
        const float* __restrict__ b,
        const float* __restrict__ g,
        const float* __restrict__ be,
        float* __restrict__ out) {
    int warp = threadIdx.x >> 5;
    int n = blockIdx.x * WPB + warp;
    if (n >= NN) return;
    int lane = threadIdx.x & 31;
    int head = lane >> 3;

    int beg = g_rowstart[n];
    int end = g_rowstart[n + 1];

    float er_h = g_er[n * NHEADS + head];

    float4 acc = make_float4(0.f, 0.f, 0.f, 0.f);
    float denom = 0.f;

    const float4* __restrict__ h4 = (const float4*)g_h;
    int col4 = lane;  // float4 index within row (row = 32 float4)

    int k = beg;
    for (; k + 4 <= end; k += 4) {
        int s0 = g_csrc[k];
        int s1 = g_csrc[k + 1];
        int s2 = g_csrc[k + 2];
        int s3 = g_csrc[k + 3];
        float e0 = g_el[s0 * NHEADS + head];
        float e1 = g_el[s1 * NHEADS + head];
        float e2 = g_el[s2 * NHEADS + head];
        float e3 = g_el[s3 * NHEADS + head];
        float4 h0 = h4[s0 * 32 + col4];
        float4 h1 = h4[s1 * 32 + col4];
        float4 h2 = h4[s2 * 32 + col4];
        float4 h3 = h4[s3 * 32 + col4];
        float w0 = __expf(leaky(e0 + er_h));
        float w1 = __expf(leaky(e1 + er_h));
        float w2 = __expf(leaky(e2 + er_h));
        float w3 = __expf(leaky(e3 + er_h));
        denom += w0 + w1 + w2 + w3;
        acc.x += h0.x * w0; acc.y += h0.y * w0; acc.z += h0.z * w0; acc.w += h0.w * w0;
        acc.x += h1.x * w1; acc.y += h1.y * w1; acc.z += h1.z * w1; acc.w += h1.w * w1;
        acc.x += h2.x * w2; acc.y += h2.y * w2; acc.z += h2.z * w2; acc.w += h2.w * w2;
        acc.x += h3.x * w3; acc.y += h3.y * w3; acc.z += h3.z * w3; acc.w += h3.w * w3;
    }
    for (; k < end; k++) {
        int s = g_csrc[k];
        float w = __expf(leaky(g_el[s * NHEADS + head] + er_h));
        float4 h = h4[s * 32 + col4];
        denom += w;
        acc.x += h.x * w; acc.y += h.y * w; acc.z += h.z * w; acc.w += h.w * w;
    }

    float invd = 1.f / fmaxf(denom, 1e-9f);

    float4 b4 = ((const float4*)b)[lane];
    float4 v;
    v.x = acc.x * invd + b4.x;
    v.y = acc.y * invd + b4.y;
    v.z = acc.z * invd + b4.z;
    v.w = acc.w * invd + b4.w;

    // LayerNorm across 128 features held 4-per-lane
    float s1 = v.x + v.y + v.z + v.w;
#pragma unroll
    for (int o = 16; o > 0; o >>= 1) s1 += __shfl_xor_sync(0xffffffffu, s1, o);
    float mu = s1 * (1.f / HID);

    float cx = v.x - mu, cy = v.y - mu, cz = v.z - mu, cw = v.w - mu;
    float s2 = cx * cx + cy * cy + cz * cz + cw * cw;
#pragma unroll
    for (int o = 16; o > 0; o >>= 1) s2 += __shfl_xor_sync(0xffffffffu, s2, o);
    float rstd = rsqrtf(s2 * (1.f / HID) + LN_EPS);

    float4 g4 = ((const float4*)g)[lane];
    float4 be4 = ((const float4*)be)[lane];
    float4 y;
    y.x = cx * rstd * g4.x + be4.x;
    y.y = cy * rstd * g4.y + be4.y;
    y.z = cz * rstd * g4.z + be4.z;
    y.w = cw * rstd * g4.w + be4.w;
    y.x = y.x > 0.f ? y.x : expm1f(y.x);
    y.y = y.y > 0.f ? y.y : expm1f(y.y);
    y.z = y.z > 0.f ? y.z : expm1f(y.z);
    y.w = y.w > 0.f ? y.w : expm1f(y.w);

    ((float4*)out)[n * 32 + lane] = y;
}

// ---------------- launch ----------------
static void run_layer(const float* feats_in, const float* W, const float* al,
                      const float* ar, const float* b, const float* g,
                      const float* be, float* out) {
    gemm_elr_kernel<<<(NN + 63) / 64, 256>>>(feats_in, W, al, ar);
    node_kernel<<<(NN + WPB - 1) / WPB, WPB * 32>>>(b, g, be, out);
}

extern "C" void kernel_launch(void* const* d_in, const int* in_sizes, int n_in,
                              void* d_out, int out_size) {
    const float* features = (const float*)d_in[0];
    const int* src = (const int*)d_in[1];
    const int* dst = (const int*)d_in[2];
    const float* W0 = (const float*)d_in[3];
    const float* al0 = (const float*)d_in[4];
    const float* ar0 = (const float*)d_in[5];
    const float* b0 = (const float*)d_in[6];
    const float* g0 = (const float*)d_in[7];
    const float* be0 = (const float*)d_in[8];
    const float* W1 = (const float*)d_in[9];
    const float* al1 = (const float*)d_in[10];
    const float* ar1 = (const float*)d_in[11];
    const float* b1 = (const float*)d_in[12];
    const float* g1 = (const float*)d_in[13];
    const float* be1 = (const float*)d_in[14];
    float* out = (float*)d_out;

    // CSR build (same graph both layers)
    zero_counts<<<(NN + 255) / 256, 256>>>();
    hist_kernel<<<(EE + 255) / 256, 256>>>(dst);
    scan_kernel<<<1, 1024>>>();
    scatter_kernel<<<(EE + 255) / 256, 256>>>(src, dst);

    float* feat_ptr = nullptr;
    cudaGetSymbolAddress((void**)&feat_ptr, g_feat);

    run_layer(features, W0, al0, ar0, b0, g0, be0, feat_ptr);
    run_layer(feat_ptr, W1, al1, ar1, b1, g1, be1, out);
}

// round 5
// speedup vs baseline: 2.7359x; 1.1839x over previous
#include <cuda_runtime.h>
#include <math.h>

#define NN 50000
#define EE 800000
#define DIN 128
#define HID 128
#define NHEADS 4
#define DHEAD 32
#define NEG_SLOPE 0.2f
#define LN_EPS 1e-5f
#define WPB 8   // warps (nodes) per block in node_kernel

// ---------------- scratch ----------------
__device__ float g_h[NN * HID];
__device__ float g_feat[NN * HID];
__device__ float g_el[NN * NHEADS];
__device__ float g_er[NN * NHEADS];
__device__ int   g_count[NN];
__device__ int   g_cursor[NN];
__device__ int   g_rowstart[NN + 1];
__device__ int   g_csrc[EE];

__device__ __forceinline__ float leaky(float v) {
    return v >= 0.f ? v : NEG_SLOPE * v;
}

// ---------------- CSR build ----------------
__global__ void zero_counts() {
    int i = blockIdx.x * blockDim.x + threadIdx.x;
    if (i < NN) g_count[i] = 0;
}

__global__ void hist_kernel(const int* __restrict__ dst) {
    int e = blockIdx.x * blockDim.x + threadIdx.x;
    if (e < EE) atomicAdd(&g_count[dst[e]], 1);
}

__global__ void scan_kernel() {
    const int T = 1024;
    const int CH = (NN + T - 1) / T;  // 49
    int t = threadIdx.x;
    int base = t * CH;
    int sum = 0;
    for (int i = 0; i < CH; i++) {
        int idx = base + i;
        if (idx < NN) sum += g_count[idx];
    }
    __shared__ int sm[T];
    sm[t] = sum;
    __syncthreads();
    for (int off = 1; off < T; off <<= 1) {
        int v = (t >= off) ? sm[t - off] : 0;
        __syncthreads();
        sm[t] += v;
        __syncthreads();
    }
    int run = sm[t] - sum;
    for (int i = 0; i < CH; i++) {
        int idx = base + i;
        if (idx < NN) {
            g_rowstart[idx] = run;
            g_cursor[idx] = run;
            run += g_count[idx];
        }
    }
    if (t == T - 1) g_rowstart[NN] = sm[T - 1];
}

__global__ void scatter_kernel(const int* __restrict__ src,
                               const int* __restrict__ dst) {
    int e = blockIdx.x * blockDim.x + threadIdx.x;
    if (e < EE) {
        int pos = atomicAdd(&g_cursor[dst[e]], 1);
        g_csrc[pos] = src[e];
    }
}

// ---------------- GEMM (128x128 tile, 8x8 per thread) + fused el/er ----------
#define TM 128
#define TK 16

__global__ void __launch_bounds__(256) gemm_elr_kernel(
        const float* __restrict__ X,
        const float* __restrict__ W,
        const float* __restrict__ al,
        const float* __restrict__ ar) {
    __shared__ float xs[TK][TM + 4];  // transposed: xs[k][row]
    __shared__ float ws[TK][HID];     // ws[k][col]
    int t = threadIdx.x;              // 256
    int tx = t & 15;                  // col group (cols tx*8 .. +8)
    int ty = t >> 4;                  // row group (rows ty*8 .. +8)
    int row0 = blockIdx.x * TM;

    int head = tx >> 2;               // cols tx*8..tx*8+7 all in head tx>>2
    int sub = (tx & 3) * 8;           // offset within head's 32 cols

    // attention vectors for this thread's 8 columns
    float al8[8], ar8[8];
#pragma unroll
    for (int j = 0; j < 8; j++) {
        al8[j] = al[head * DHEAD + sub + j];
        ar8[j] = ar[head * DHEAD + sub + j];
    }

    float acc[8][8];
#pragma unroll
    for (int i = 0; i < 8; i++)
#pragma unroll
        for (int j = 0; j < 8; j++) acc[i][j] = 0.f;

    for (int k0 = 0; k0 < DIN; k0 += TK) {
        // stage X tile (128 rows x 16 cols) transposed into xs
#pragma unroll
        for (int i = 0; i < 2; i++) {
            int idx = t * 2 + i;       // 0..511
            int r = idx >> 2;          // row 0..127
            int q = idx & 3;           // float4 within the 16-col slab
            int gr = row0 + r;
            float4 v = make_float4(0.f, 0.f, 0.f, 0.f);
            if (gr < NN) v = ((const float4*)X)[gr * (DIN / 4) + (k0 / 4) + q];
            xs[q * 4 + 0][r] = v.x;
            xs[q * 4 + 1][r] = v.y;
            xs[q * 4 + 2][r] = v.z;
            xs[q * 4 + 3][r] = v.w;
        }
        // stage W tile (16 rows x 128 cols)
#pragma unroll
        for (int i = 0; i < 2; i++) {
            int idx = t * 2 + i;       // 0..511
            int k = idx >> 5;          // 0..15
            int q = idx & 31;          // float4 col
            float4 v = ((const float4*)W)[(k0 + k) * (HID / 4) + q];
            ((float4*)ws[k])[q] = v;
        }
        __syncthreads();
#pragma unroll
        for (int k = 0; k < TK; k++) {
            float a[8], bb[8];
            *(float4*)&a[0] = *(const float4*)&xs[k][ty * 8];
            *(float4*)&a[4] = *(const float4*)&xs[k][ty * 8 + 4];
            *(float4*)&bb[0] = *(const float4*)&ws[k][tx * 8];
            *(float4*)&bb[4] = *(const float4*)&ws[k][tx * 8 + 4];
#pragma unroll
            for (int i = 0; i < 8; i++)
#pragma unroll
                for (int j = 0; j < 8; j++) acc[i][j] += a[i] * bb[j];
        }
        __syncthreads();
    }

    // epilogue: store h, compute el/er
#pragma unroll
    for (int i = 0; i < 8; i++) {
        int gr = row0 + ty * 8 + i;
        if (gr < NN) {
            float4 h0 = make_float4(acc[i][0], acc[i][1], acc[i][2], acc[i][3]);
            float4 h1 = make_float4(acc[i][4], acc[i][5], acc[i][6], acc[i][7]);
            ((float4*)g_h)[gr * 32 + tx * 2] = h0;
            ((float4*)g_h)[gr * 32 + tx * 2 + 1] = h1;

            float vl = 0.f, vr = 0.f;
#pragma unroll
            for (int j = 0; j < 8; j++) {
                vl += acc[i][j] * al8[j];
                vr += acc[i][j] * ar8[j];
            }
            // reduce across the 4 threads (tx&3 group) sharing this head
            vl += __shfl_xor_sync(0xffffffffu, vl, 1);
            vr += __shfl_xor_sync(0xffffffffu, vr, 1);
            vl += __shfl_xor_sync(0xffffffffu, vl, 2);
            vr += __shfl_xor_sync(0xffffffffu, vr, 2);
            if ((tx & 3) == 0) {
                g_el[gr * NHEADS + head] = vl;
                g_er[gr * NHEADS + head] = vr;
            }
        }
    }
}

// ---------------- warp-per-node gather + softmax + aggregate + LN + ELU --------
__global__ void __launch_bounds__(WPB * 32) node_kernel(
        const float* __restrict__ b,
        const float* __restrict__ g,
        const float* __restrict__ be,
        float* __restrict__ out) {
    int warp = threadIdx.x >> 5;
    int n = blockIdx.x * WPB + warp;
    if (n >= NN) return;
    int lane = threadIdx.x & 31;
    int head = lane >> 3;

    int beg = g_rowstart[n];
    int end = g_rowstart[n + 1];

    float er_h = g_er[n * NHEADS + head];

    float4 acc = make_float4(0.f, 0.f, 0.f, 0.f);
    float denom = 0.f;

    const float4* __restrict__ h4 = (const float4*)g_h;
    int col4 = lane;

    int k = beg;
    for (; k + 4 <= end; k += 4) {
        int s0 = g_csrc[k];
        int s1 = g_csrc[k + 1];
        int s2 = g_csrc[k + 2];
        int s3 = g_csrc[k + 3];
        float e0 = g_el[s0 * NHEADS + head];
        float e1 = g_el[s1 * NHEADS + head];
        float e2 = g_el[s2 * NHEADS + head];
        float e3 = g_el[s3 * NHEADS + head];
        float4 h0 = h4[s0 * 32 + col4];
        float4 h1 = h4[s1 * 32 + col4];
        float4 h2 = h4[s2 * 32 + col4];
        float4 h3 = h4[s3 * 32 + col4];
        float w0 = __expf(leaky(e0 + er_h));
        float w1 = __expf(leaky(e1 + er_h));
        float w2 = __expf(leaky(e2 + er_h));
        float w3 = __expf(leaky(e3 + er_h));
        denom += w0 + w1 + w2 + w3;
        acc.x += h0.x * w0; acc.y += h0.y * w0; acc.z += h0.z * w0; acc.w += h0.w * w0;
        acc.x += h1.x * w1; acc.y += h1.y * w1; acc.z += h1.z * w1; acc.w += h1.w * w1;
        acc.x += h2.x * w2; acc.y += h2.y * w2; acc.z += h2.z * w2; acc.w += h2.w * w2;
        acc.x += h3.x * w3; acc.y += h3.y * w3; acc.z += h3.z * w3; acc.w += h3.w * w3;
    }
    for (; k < end; k++) {
        int s = g_csrc[k];
        float w = __expf(leaky(g_el[s * NHEADS + head] + er_h));
        float4 h = h4[s * 32 + col4];
        denom += w;
        acc.x += h.x * w; acc.y += h.y * w; acc.z += h.z * w; acc.w += h.w * w;
    }

    float invd = 1.f / fmaxf(denom, 1e-9f);

    float4 b4 = ((const float4*)b)[lane];
    float4 v;
    v.x = acc.x * invd + b4.x;
    v.y = acc.y * invd + b4.y;
    v.z = acc.z * invd + b4.z;
    v.w = acc.w * invd + b4.w;

    float s1 = v.x + v.y + v.z + v.w;
#pragma unroll
    for (int o = 16; o > 0; o >>= 1) s1 += __shfl_xor_sync(0xffffffffu, s1, o);
    float mu = s1 * (1.f / HID);

    float cx = v.x - mu, cy = v.y - mu, cz = v.z - mu, cw = v.w - mu;
    float s2 = cx * cx + cy * cy + cz * cz + cw * cw;
#pragma unroll
    for (int o = 16; o > 0; o >>= 1) s2 += __shfl_xor_sync(0xffffffffu, s2, o);
    float rstd = rsqrtf(s2 * (1.f / HID) + LN_EPS);

    float4 g4 = ((const float4*)g)[lane];
    float4 be4 = ((const float4*)be)[lane];
    float4 y;
    y.x = cx * rstd * g4.x + be4.x;
    y.y = cy * rstd * g4.y + be4.y;
    y.z = cz * rstd * g4.z + be4.z;
    y.w = cw * rstd * g4.w + be4.w;
    y.x = y.x > 0.f ? y.x : expm1f(y.x);
    y.y = y.y > 0.f ? y.y : expm1f(y.y);
    y.z = y.z > 0.f ? y.z : expm1f(y.z);
    y.w = y.w > 0.f ? y.w : expm1f(y.w);

    ((float4*)out)[n * 32 + lane] = y;
}

// ---------------- launch ----------------
extern "C" void kernel_launch(void* const* d_in, const int* in_sizes, int n_in,
                              void* d_out, int out_size) {
    const float* features = (const float*)d_in[0];
    const int* src = (const int*)d_in[1];
    const int* dst = (const int*)d_in[2];
    const float* W0 = (const float*)d_in[3];
    const float* al0 = (const float*)d_in[4];
    const float* ar0 = (const float*)d_in[5];
    const float* b0 = (const float*)d_in[6];
    const float* g0 = (const float*)d_in[7];
    const float* be0 = (const float*)d_in[8];
    const float* W1 = (const float*)d_in[9];
    const float* al1 = (const float*)d_in[10];
    const float* ar1 = (const float*)d_in[11];
    const float* b1 = (const float*)d_in[12];
    const float* g1 = (const float*)d_in[13];
    const float* be1 = (const float*)d_in[14];
    float* out = (float*)d_out;

    // lazily-created side stream + events (created on the first, non-captured,
    // correctness call; reused identically on every subsequent call)
    static cudaStream_t s2 = nullptr;
    static cudaEvent_t evFork = nullptr, evJoin = nullptr;
    if (!s2) {
        cudaStreamCreateWithFlags(&s2, cudaStreamNonBlocking);
        cudaEventCreateWithFlags(&evFork, cudaEventDisableTiming);
        cudaEventCreateWithFlags(&evJoin, cudaEventDisableTiming);
    }

    float* feat_ptr = nullptr;
    cudaGetSymbolAddress((void**)&feat_ptr, g_feat);

    const int gemm_grid = (NN + TM - 1) / TM;

    // fork: CSR build on s2, concurrent with layer-0 GEMM on the main stream
    cudaEventRecord(evFork, 0);
    cudaStreamWaitEvent(s2, evFork, 0);
    zero_counts<<<(NN + 255) / 256, 256, 0, s2>>>();
    hist_kernel<<<(EE + 255) / 256, 256, 0, s2>>>(dst);
    scan_kernel<<<1, 1024, 0, s2>>>();
    scatter_kernel<<<(EE + 255) / 256, 256, 0, s2>>>(src, dst);
    cudaEventRecord(evJoin, s2);

    gemm_elr_kernel<<<gemm_grid, 256>>>(features, W0, al0, ar0);
    cudaStreamWaitEvent(0, evJoin, 0);  // join before aggregation needs CSR

    node_kernel<<<(NN + WPB - 1) / WPB, WPB * 32>>>(b0, g0, be0, feat_ptr);

    gemm_elr_kernel<<<gemm_grid, 256>>>(feat_ptr, W1, al1, ar1);
    node_kernel<<<(NN + WPB - 1) / WPB, WPB * 32>>>(b1, g1, be1, out);
}